// round 7
// baseline (speedup 1.0000x reference)
#include <cuda_runtime.h>
#include <cuda_bf16.h>
#include <math.h>

#define BB 16
#define CC 256
#define HH 96
#define WW 128
#define HW (HH * WW)          // 12288
#define HW4 (HW / 4)          // 3072 float4 per plane
#define OUT_H 12
#define OUT_W 16
#define NN (OUT_H * OUT_W)    // 192
#define KH 8
#define KW 8
#define QQ 4
#define HIDDEN 128
#define TAU_INV 10.0f

#define SCALE_BLOCKS 16
#define FUSE_BLOCKS (BB * CC)           // 4096: one block per (b,c) plane
#define TOTAL_BLOCKS (SCALE_BLOCKS + FUSE_BLOCKS)

// ---------------- device scratch (static, zero-initialized) ----------------
__device__ float    g_scale[BB * CC];   // zero-init; written only when Wb != 0
__device__ int      g_viol;
__device__ unsigned g_acnt;
__device__ unsigned g_scnt;
__device__ unsigned g_ready;
__device__ unsigned g_done;

__device__ __forceinline__ float sigmoidf_(float z) {
    return __fdividef(1.0f, 1.0f + __expf(-z));
}

union SmemU {
    struct {
        float  s[NN];
        float  rr[NN];
        float2 red[256];
        float  qv[CC * QQ];
        float  ts[HIDDEN * QQ];
    } sc;
    struct {
        float dadb[2];
        float Ms[CC];
    } fu;
};

#define SCALE4(v, cf) do { (v).x *= (cf); (v).y *= (cf); (v).z *= (cf); (v).w *= (cf); } while (0)

__global__ void __launch_bounds__(256) mono_kernel(const float* __restrict__ x,
                                                   const float* __restrict__ wf,
                                                   const float* __restrict__ w1,
                                                   const float* __restrict__ w2,
                                                   float* __restrict__ out) {
    __shared__ SmemU sm;
    int bid = blockIdx.x;
    int tid = threadIdx.x;

    if (bid >= SCALE_BLOCKS) {
        // ================= fuse role: one block per plane =================
        int plane = bid - SCALE_BLOCKS;          // b*C + c
        int b = plane >> 8;
        int c = plane & (CC - 1);

        const float4* src = (const float4*)x + (size_t)plane * HW4 + tid;
        float4*       dst = (float4*)out      + (size_t)plane * HW4 + tid;

        // batch0 loads in flight while we analyze the wf row
        float4 v0 = __ldcs(src);
        float4 v1 = __ldcs(src + 256);
        float4 v2 = __ldcs(src + 512);
        float4 v3 = __ldcs(src + 768);

        float wa = wf[c * 512 + tid];
        float wb = wf[c * 512 + 256 + tid];
        int bad = ((wa != 0.0f) | (wb != 0.0f)) & (tid != c);
        if (tid == c) { sm.fu.dadb[0] = wa; sm.fu.dadb[1] = wb; }
        int nondiag = __syncthreads_or(bad);

        if (!nondiag) {
            float da = sm.fu.dadb[0], db = sm.fu.dadb[1];
            float coeff;
            if (db != 0.0f) {
                if (tid == 0) { while (atomicAdd(&g_ready, 0u) == 0u) { } }
                __syncthreads();
                __threadfence();
                coeff = da + db * g_scale[plane];
            } else {
                coeff = da;
            }
            // 3-stage pipeline: issue next batch's loads before storing current
            float4 u0 = __ldcs(src + 1024);
            float4 u1 = __ldcs(src + 1280);
            float4 u2 = __ldcs(src + 1536);
            float4 u3 = __ldcs(src + 1792);
            SCALE4(v0, coeff); SCALE4(v1, coeff); SCALE4(v2, coeff); SCALE4(v3, coeff);
            __stcs(dst,        v0);
            __stcs(dst + 256,  v1);
            __stcs(dst + 512,  v2);
            __stcs(dst + 768,  v3);
            v0 = __ldcs(src + 2048);
            v1 = __ldcs(src + 2304);
            v2 = __ldcs(src + 2560);
            v3 = __ldcs(src + 2816);
            SCALE4(u0, coeff); SCALE4(u1, coeff); SCALE4(u2, coeff); SCALE4(u3, coeff);
            __stcs(dst + 1024, u0);
            __stcs(dst + 1280, u1);
            __stcs(dst + 1536, u2);
            __stcs(dst + 1792, u3);
            SCALE4(v0, coeff); SCALE4(v1, coeff); SCALE4(v2, coeff); SCALE4(v3, coeff);
            __stcs(dst + 2048, v0);
            __stcs(dst + 2304, v1);
            __stcs(dst + 2560, v2);
            __stcs(dst + 2816, v3);
        } else {
            // general per-row matvec (correctness-grade slow path)
            if (tid == 0) { while (atomicAdd(&g_ready, 0u) == 0u) { } }
            __syncthreads();
            __threadfence();
            sm.fu.Ms[tid] = wa + wb * g_scale[b * CC + tid];
            __syncthreads();

            const float4* xb4 = (const float4*)x + (size_t)b * CC * HW4 + tid;
            for (int seg = 0; seg < 6; seg++) {
                float4 a0 = make_float4(0.f, 0.f, 0.f, 0.f);
                float4 a1 = make_float4(0.f, 0.f, 0.f, 0.f);
                const float4* p = xb4 + seg * 512;
                for (int k = 0; k < CC; k++) {
                    float m = sm.fu.Ms[k];
                    float4 q0 = p[(size_t)k * HW4];
                    float4 q1 = p[(size_t)k * HW4 + 256];
                    a0.x += m * q0.x; a0.y += m * q0.y; a0.z += m * q0.z; a0.w += m * q0.w;
                    a1.x += m * q1.x; a1.y += m * q1.y; a1.z += m * q1.z; a1.w += m * q1.w;
                }
                dst[seg * 512]       = a0;
                dst[seg * 512 + 256] = a1;
            }
        }
    } else {
        // ================= scale role =================
        int b = bid;
        {
            int viol = 0;
            #pragma unroll 4
            for (int r = 0; r < 16; r++) {
                int c = b * 16 + r;
                float a0 = wf[c * 512 + tid];
                float a1 = wf[c * 512 + 256 + tid];
                if (a0 != 0.0f && tid != c) viol |= 1;
                if (a1 != 0.0f) { viol |= 2; if (tid != c) viol |= 1; }
            }
            viol = __syncthreads_or(viol);
            if (tid == 0) {
                if (viol) atomicOr(&g_viol, viol);
                __threadfence();
                atomicAdd(&g_acnt, 1u);
                while (atomicAdd(&g_acnt, 0u) < SCALE_BLOCKS) { }
            }
            __syncthreads();
        }
        int viol = g_viol;
        if ((viol & 2) == 0) {
            if (tid == 0 && b == 0) { __threadfence(); atomicExch(&g_ready, 1u); }
        } else {
            const float quant[QQ] = {0.25f, 0.5f, 0.75f, 0.95f};
            for (int c = 0; c < CC; c++) {
                int bc = b * CC + c;
                if (tid < NN) {
                    int oh = tid >> 4, ow = tid & 15;
                    const float* base = x + (size_t)bc * HW + oh * (KH * WW) + ow * KW;
                    float acc = 0.0f;
                    #pragma unroll
                    for (int r = 0; r < KH; r++) {
                        float4 a = *(const float4*)(base + r * WW);
                        float4 bb = *(const float4*)(base + r * WW + 4);
                        acc += a.x + a.y + a.z + a.w + bb.x + bb.y + bb.z + bb.w;
                    }
                    sm.sc.s[tid] = acc * (1.0f / 64.0f);
                }
                __syncthreads();
                if (tid < NN) {
                    float xi = sm.sc.s[tid];
                    float acc = 1.0f;
                    #pragma unroll 4
                    for (int j = 0; j < NN; j++) acc += sigmoidf_((xi - sm.sc.s[j]) * TAU_INV);
                    sm.sc.rr[tid] = acc;
                }
                __syncthreads();
                for (int q = 0; q < QQ; q++) {
                    float tq = 1.0f + quant[q] * (float)(NN - 1);
                    float e = 0.0f, ex = 0.0f;
                    if (tid < NN) {
                        e  = __expf(-fabsf(sm.sc.rr[tid] - tq) * TAU_INV);
                        ex = e * sm.sc.s[tid];
                    }
                    sm.sc.red[tid] = make_float2(e, ex);
                    __syncthreads();
                    for (int st = 128; st >= 1; st >>= 1) {
                        if (tid < st) {
                            float2 o = sm.sc.red[tid + st];
                            sm.sc.red[tid].x += o.x;
                            sm.sc.red[tid].y += o.y;
                        }
                        __syncthreads();
                    }
                    if (tid == 0) sm.sc.qv[c * QQ + q] = sm.sc.red[0].y / sm.sc.red[0].x;
                    __syncthreads();
                }
            }
            for (int idx = tid; idx < HIDDEN * QQ; idx += 256) {
                int h = idx >> 2, q = idx & 3;
                float acc = 0.0f;
                #pragma unroll 4
                for (int c = 0; c < CC; c++) acc += w1[h * CC + c] * sm.sc.qv[c * QQ + q];
                sm.sc.ts[idx] = fmaxf(acc, 0.0f);
            }
            __syncthreads();
            {
                int c = tid;
                float acc = 0.0f;
                #pragma unroll 4
                for (int k = 0; k < HIDDEN * QQ; k++) acc += sm.sc.ts[k] * w2[c * (HIDDEN * QQ) + k];
                g_scale[b * CC + c] = sigmoidf_(acc);
            }
            __syncthreads();
            if (tid == 0) {
                __threadfence();
                if (atomicAdd(&g_scnt, 1u) == SCALE_BLOCKS - 1) atomicExch(&g_ready, 1u);
            }
        }
    }

    // last finishing block resets per-call state for the next graph replay
    __syncthreads();
    if (threadIdx.x == 0) {
        __threadfence();
        if (atomicAdd(&g_done, 1u) == (unsigned)(gridDim.x - 1)) {
            g_viol  = 0;
            g_acnt  = 0;
            g_scnt  = 0;
            g_ready = 0;
            g_done  = 0;
            __threadfence();
        }
    }
}

// ---------------- launch ----------------
extern "C" void kernel_launch(void* const* d_in, const int* in_sizes, int n_in,
                              void* d_out, int out_size) {
    const float* x  = (const float*)d_in[0];
    const float* w1 = (const float*)d_in[1];
    const float* w2 = (const float*)d_in[2];
    const float* wf = (const float*)d_in[3];
    float* out = (float*)d_out;

    mono_kernel<<<TOTAL_BLOCKS, 256>>>(x, wf, w1, w2, out);
}